// round 14
// baseline (speedup 1.0000x reference)
#include <cuda_runtime.h>
#include <cuda_fp16.h>
#include <cstdint>

// Problem dims
static constexpr int M = 256;
static constexpr int K = 4096;
static constexpr int N = 8192;
static constexpr int SITERS = K / 128;    // 32 super-iters of BK=128
static constexpr int THREADS = 512;       // 16 warps: 4(M) x 2(N) x 2(K-team)

// SMEM layout (per 512-thread CTA, tile 256x64, BK=128):
//  [0,1024)              header (alignment)
//  [1024, +3*65536)      A fragment ring: 3 stages x 64KB
//                        stage = [kc(2)][mi(16)][ks(4)][lane(32)] x 16B
//  [197632, +2*16384)    B double buffer: per buffer 2 k-chunks x (64 rows x 128B)
static constexpr int SMEM_A = 1024;
static constexpr int SMEM_B = 1024 + 3 * 65536;        // 197632
static constexpr int SMEM_TOTAL = SMEM_B + 2 * 16384;  // 230400

// A in m16n8k16 fragment layout, fp16, built by convert kernel.
// Index: ((mi * (K/16) + ki) * 32 + lane) -> uint4 (regs a0,a1,a2,a3)
__device__ uint4 g_xa[(M / 16) * (K / 16) * 32];

// ---------------- helpers ----------------

__device__ __forceinline__ uint32_t smem_u32(const void* p) {
    uint32_t a;
    asm("{ .reg .u64 t; cvta.to.shared.u64 t, %1; cvt.u32.u64 %0, t; }"
        : "=r"(a) : "l"(p));
    return a;
}

__device__ __forceinline__ uint32_t sw128(uint32_t off) {
    return off ^ ((off >> 3) & 0x70);
}

// Dequant one 16-weight group (4 int32, low byte each = 4 x 2-bit codes)
// into 8 u32 = 16 fp16, via a 4-entry fp16 LUT + PRMT byte gather.
__device__ __forceinline__ void dequant16(const int4& p4, float n, uint32_t o[8]) {
    uint32_t b1 = (uint32_t)__half_as_ushort(__float2half_rn(n));
    uint32_t b3 = (uint32_t)__half_as_ushort(__float2half_rn(n * (1.0f / 3.0f)));
    uint32_t loT = (b1 ^ 0x8000u) | ((b3 ^ 0x8000u) << 16);  // bytes: [-n][-n/3]
    uint32_t hiT = b3 | (b1 << 16);                          // bytes: [n/3][n]
    uint32_t pv[4] = { (uint32_t)p4.x, (uint32_t)p4.y, (uint32_t)p4.z, (uint32_t)p4.w };
    #pragma unroll
    for (int q = 0; q < 4; ++q) {
        uint32_t by = pv[q] & 0xFFu;   // 4 x 2-bit codes
        uint32_t l = by & 0xFu;
        uint32_t h = by >> 4;
        uint32_t c0 = (l & 3u) * 0x22u + (l & 0xCu) * 0x880u + 0x1010u;
        uint32_t c1 = (h & 3u) * 0x22u + (h & 0xCu) * 0x880u + 0x1010u;
        o[2 * q]     = __byte_perm(loT, hiT, c0);
        o[2 * q + 1] = __byte_perm(loT, hiT, c1);
    }
}

// ---------------- kernel 0: x fp32 -> A-fragment fp16 layout ----------------

__global__ void convert_x_frag(const float* __restrict__ x) {
    int g = blockIdx.x * blockDim.x + threadIdx.x;   // 0 .. 131071
    int lane = g & 31;
    int ki = (g >> 5) & (K / 16 - 1);
    int mi = g >> 13;
    int r = lane >> 2;
    int c = (lane & 3) * 2;
    const float* base = x + (size_t)(mi * 16 + r) * K + ki * 16 + c;
    float2 v00 = *reinterpret_cast<const float2*>(base);
    float2 v10 = *reinterpret_cast<const float2*>(base + 8 * K);
    float2 v01 = *reinterpret_cast<const float2*>(base + 8);
    float2 v11 = *reinterpret_cast<const float2*>(base + 8 * K + 8);
    uint4 o;
    o.x = (uint32_t)__half_as_ushort(__float2half_rn(v00.x)) |
          ((uint32_t)__half_as_ushort(__float2half_rn(v00.y)) << 16);
    o.y = (uint32_t)__half_as_ushort(__float2half_rn(v10.x)) |
          ((uint32_t)__half_as_ushort(__float2half_rn(v10.y)) << 16);
    o.z = (uint32_t)__half_as_ushort(__float2half_rn(v01.x)) |
          ((uint32_t)__half_as_ushort(__float2half_rn(v01.y)) << 16);
    o.w = (uint32_t)__half_as_ushort(__float2half_rn(v11.x)) |
          ((uint32_t)__half_as_ushort(__float2half_rn(v11.y)) << 16);
    g_xa[g] = o;
}

// ---------------- kernel 1: fused dequant + fp16 HMMA GEMM ----------------
// Grid (128): blockIdx.x = N-tile (64 cols). CTA tile = 256(M) x 64(N), BK=128.
// TWO INDEPENDENT 256-thread pipelines ("teams"), one per 64-wide k-chunk,
// synchronized by named barriers (bar.sync 1+team). Teams share no SMEM in
// the main loop: each copies its own A half-stage, dequants its own B chunk,
// and consumes only those. This decorrelates load/MMA phases across the SM.
// End: drain cp.async, full __syncthreads, team-1 accs -> smem -> team 0 adds.

__global__ void __launch_bounds__(THREADS, 1)
linear2bit_gemm(const int4* __restrict__ wq,        // one int4 = one 16-value group
                const void* __restrict__ wn_raw,    // [NUM_GROUPS] norms (fp32 or fp16)
                const float* __restrict__ bias,     // [N]
                float* __restrict__ out)            // [M, N]
{
    extern __shared__ char smem[];
    const uint32_t sb = smem_u32(smem);
    const int tid = threadIdx.x;
    const int wid = tid >> 5;
    const int lid = tid & 31;
    const int ntile = blockIdx.x;                   // 64-col tile

    // ---- runtime dtype probe for weight_norm ----
    const float* wnf = (const float*)wn_raw;
    const __half* wnh = (const __half*)wn_raw;
    const float probe = __ldg(wnf);
    const bool norm_f32 = (probe > 6e-5f && probe < 0.06f);

    // team / compute-warp decomposition (teams interleaved across SMSPs)
    const int team = (wid >> 2) & 1;                       // k-chunk owner
    const int cwid = (wid & 3) | ((wid >> 3) << 2);        // 0..7 within team
    const int ttid = cwid * 32 + lid;                      // 0..255 within team
    const int warp_m = cwid >> 1;    // 4 x 64 rows
    const int warp_n = cwid & 1;     // 2 x 32 cols
    const int bar_id = 1 + team;     // named barrier per team

    // B ldmatrix per-lane unswizzled bases (two 16-row groups per warp)
    uint32_t brow[2];
    #pragma unroll
    for (int p = 0; p < 2; ++p)
        brow[p] = (uint32_t)((warp_n * 32 + p * 16 + (lid & 15)) * 128 + (lid >> 4) * 16);

    // ---- A cp.async (team-local: each team fills its own kc=team half) ----
    // Thread covers 8 x 16B chunks: flat = ttid + 256j; t2 = flat>>5 = cwid + 8j;
    //   ks = cwid&3 (const); mi = (cwid>>2) + 2j.
    // src uint4 = si*256 + [mi*8192 + team*128 + ks*32 + lane]
    //           = si*256 + a_off0 + j*16384
    // dst chunk = team half + ttid*16 + j*4096 (verified == (mi*4+ks)*32+lane)
    const uint32_t a_off0 =
        (uint32_t)((cwid >> 2) * 8192 + team * 128 + (cwid & 3) * 32 + lid);
    const uint32_t a_dst0 = (uint32_t)(team * 32768 + ttid * 16);
    auto cp_a = [&](int si, int slot) {
        const uint4* srcb = g_xa + (size_t)si * 256 + a_off0;
        uint32_t sdst = sb + SMEM_A + (uint32_t)slot * 65536u + a_dst0;
        #pragma unroll
        for (int j = 0; j < 8; ++j) {
            const uint4* src = srcb + j * 16384;
            asm volatile("cp.async.cg.shared.global [%0], [%1], 16;"
                         :: "r"(sdst + (uint32_t)j * 4096u), "l"(src) : "memory");
        }
        asm volatile("cp.async.commit_group;" ::: "memory");
    };

    // A LDS byte base within a stage for this warp/lane (team half + warp rows)
    const uint32_t a_lds_off =
        (uint32_t)team * 32768u + (uint32_t)((warp_m * 4 * 4) * 32 + lid) * 16u;

    float acc[4][4][4];
    #pragma unroll
    for (int mt = 0; mt < 4; ++mt)
        #pragma unroll
        for (int nt = 0; nt < 4; ++nt)
            #pragma unroll
            for (int e = 0; e < 4; ++e) acc[mt][nt][e] = 0.0f;

    // B staging (team-local): 256 groups per chunk over 256 team threads
    const int br = ttid >> 2;       // B row in tile (0..63)
    const int bj = ttid & 3;        // group within this team's k-chunk (0..3)
    const int bg_base = (ntile * 64 + br) * 256 + team * 4 + bj;   // + si*8

    int4  bv;
    float bn;

    auto ldg_b = [&](int si) {
        int gidx = bg_base + si * 8;
        bv = __ldg(wq + gidx);
        bn = norm_f32 ? __ldg(wnf + gidx) : __half2float(__ldg(wnh + gidx));
    };
    auto sts_b = [&](int b) {
        char* bbuf = smem + SMEM_B + b * 16384 + team * 8192;
        uint32_t o[8];
        dequant16(bv, bn, o);
        uint32_t off = (uint32_t)(br * 128 + bj * 32);
        *reinterpret_cast<int4*>(bbuf + sw128(off)) =
            make_int4((int)o[0], (int)o[1], (int)o[2], (int)o[3]);
        *reinterpret_cast<int4*>(bbuf + sw128(off + 16)) =
            make_int4((int)o[4], (int)o[5], (int)o[6], (int)o[7]);
    };

    // ---- prologue (team-local) ----
    ldg_b(0);
    cp_a(0, 0);
    cp_a(1, 1);
    sts_b(0);
    asm volatile("cp.async.wait_group 1;" ::: "memory");   // stage 0 (our half) ready
    asm volatile("bar.sync %0, %1;" :: "r"(bar_id), "n"(256) : "memory");

    int s_cur = 0;   // (si) % 3
    int s_nxt = 2;   // (si+2) % 3

    #pragma unroll 1
    for (int si = 0; si < SITERS; ++si) {
        const int b = si & 1;
        if (si + 1 < SITERS) ldg_b(si + 1);

        const char* aslot = smem + SMEM_A + s_cur * 65536 + a_lds_off;
        const uint32_t bb = sb + SMEM_B + (uint32_t)b * 16384u + (uint32_t)team * 8192u;

        #pragma unroll
        for (int ks = 0; ks < 4; ++ks) {
            const uint32_t kb = (uint32_t)(ks * 32);   // 16 halves per k-step

            // A fragments for this ks: 4 x LDS.128 (mt = 0..3)
            uint4 af[4];
            #pragma unroll
            for (int mt = 0; mt < 4; ++mt)
                af[mt] = *reinterpret_cast<const uint4*>(
                    aslot + (mt * 4 + ks) * 32 * 16);

            uint32_t bf[2][4];
            #pragma unroll
            for (int p = 0; p < 2; ++p) {
                uint32_t addr = bb + sw128(brow[p] + kb);
                asm volatile(
                    "ldmatrix.sync.aligned.m8n8.x4.shared.b16 {%0,%1,%2,%3}, [%4];"
                    : "=r"(bf[p][0]), "=r"(bf[p][1]), "=r"(bf[p][2]), "=r"(bf[p][3])
                    : "r"(addr));
            }
            #pragma unroll
            for (int mt = 0; mt < 4; ++mt) {
                #pragma unroll
                for (int nt = 0; nt < 4; ++nt) {
                    uint32_t b0 = bf[nt >> 1][nt & 1];
                    uint32_t b1 = bf[nt >> 1][(nt & 1) + 2];
                    asm volatile(
                        "mma.sync.aligned.m16n8k16.row.col.f32.f16.f16.f32 "
                        "{%0,%1,%2,%3}, {%4,%5,%6,%7}, {%8,%9}, {%0,%1,%2,%3};"
                        : "+f"(acc[mt][nt][0]), "+f"(acc[mt][nt][1]),
                          "+f"(acc[mt][nt][2]), "+f"(acc[mt][nt][3])
                        : "r"(af[mt].x), "r"(af[mt].y),
                          "r"(af[mt].z), "r"(af[mt].w),
                          "r"(b0), "r"(b1));
                }
            }
        }

        if (si + 1 < SITERS) sts_b(b ^ 1);

        // Issue our half of stage si+2; at the tail commit an EMPTY group so
        // wait_group 1 keeps counting correctly.
        if (si + 2 < SITERS) cp_a(si + 2, s_nxt);
        else asm volatile("cp.async.commit_group;" ::: "memory");
        asm volatile("cp.async.wait_group 1;" ::: "memory");   // stage si+1 ready
        asm volatile("bar.sync %0, %1;" :: "r"(bar_id), "n"(256) : "memory");

        s_cur = (s_cur == 2) ? 0 : s_cur + 1;
        s_nxt = (s_nxt == 2) ? 0 : s_nxt + 1;
    }

    // ---- drain the async pipe, then full-CTA sync before reusing the A ring ----
    asm volatile("cp.async.wait_group 0;" ::: "memory");
    __syncthreads();

    // ---- split-K reduction: team 1 -> smem -> team 0 adds ----
    // Reuse the A ring region. Per team-1 warp: 16 float4 chunks laid out
    // [chunk(16)][lane(32)] so loads are conflict-free.
    if (team == 1) {
        char* red = smem + SMEM_A + cwid * 8192 + lid * 16;
        #pragma unroll
        for (int mt = 0; mt < 4; ++mt)
            #pragma unroll
            for (int nt = 0; nt < 4; ++nt)
                *reinterpret_cast<float4*>(red + (mt * 4 + nt) * 512) =
                    make_float4(acc[mt][nt][0], acc[mt][nt][1],
                                acc[mt][nt][2], acc[mt][nt][3]);
    }
    __syncthreads();

    if (team == 0) {
        const char* red = smem + SMEM_A + cwid * 8192 + lid * 16;
        const int mbase = warp_m * 64;
        const int nbase = ntile * 64 + warp_n * 32;
        const int rq = lid >> 2;             // row within m16 (0..7)
        const int cq = (lid & 3) * 2;        // col within n8 (0,2,4,6)
        #pragma unroll
        for (int mt = 0; mt < 4; ++mt) {
            #pragma unroll
            for (int nt = 0; nt < 4; ++nt) {
                float4 r = *reinterpret_cast<const float4*>(red + (mt * 4 + nt) * 512);
                int m0 = mbase + mt * 16 + rq;
                int n0 = nbase + nt * 8 + cq;
                float2 bsv = __ldg(reinterpret_cast<const float2*>(bias + n0));
                float2 v0, v1;
                v0.x = acc[mt][nt][0] + r.x + bsv.x;
                v0.y = acc[mt][nt][1] + r.y + bsv.y;
                v1.x = acc[mt][nt][2] + r.z + bsv.x;
                v1.y = acc[mt][nt][3] + r.w + bsv.y;
                *reinterpret_cast<float2*>(out + (size_t)m0 * N + n0) = v0;
                *reinterpret_cast<float2*>(out + (size_t)(m0 + 8) * N + n0) = v1;
            }
        }
    }
}

// ---------------- launch ----------------

extern "C" void kernel_launch(void* const* d_in, const int* in_sizes, int n_in,
                              void* d_out, int out_size) {
    (void)in_sizes; (void)n_in; (void)out_size;
    const float* x    = (const float*)d_in[0];
    const int4*  wq   = (const int4*)d_in[1];    // [NUM_GROUPS] groups of 4 int32
    const void*  wn   = (const void*)d_in[2];    // [NUM_GROUPS] norms
    const float* bias = (const float*)d_in[3];
    float*       out  = (float*)d_out;

    cudaFuncSetAttribute(linear2bit_gemm,
                         cudaFuncAttributeMaxDynamicSharedMemorySize, SMEM_TOTAL);

    convert_x_frag<<<(M / 16) * (K / 16) * 32 / 256, 256>>>(x);
    linear2bit_gemm<<<N / 64, THREADS, SMEM_TOTAL>>>(wq, wn, bias, out);
}

// round 15
// speedup vs baseline: 1.0172x; 1.0172x over previous
#include <cuda_runtime.h>
#include <cuda_fp16.h>
#include <cstdint>

// Problem dims
static constexpr int M = 256;
static constexpr int K = 4096;
static constexpr int N = 8192;
static constexpr int SITERS = K / 128;    // 32 super-iters of BK=128
static constexpr int THREADS = 512;       // 16 warps: 4(M) x 2(N) x 2(K-team)

// SMEM layout (per 512-thread CTA, tile 256x64, BK=128):
//  [0,1024)              header (alignment)
//  [1024, +3*65536)      A fragment ring: 3 stages x 64KB
//                        stage = [kc(2)][mi(16)][ks(4)][lane(32)] x 16B
//  [197632, +2*16384)    B double buffer: per buffer 2 k-chunks x (64 rows x 128B)
static constexpr int SMEM_A = 1024;
static constexpr int SMEM_B = 1024 + 3 * 65536;        // 197632
static constexpr int SMEM_TOTAL = SMEM_B + 2 * 16384;  // 230400

// A in m16n8k16 fragment layout, fp16, built by convert kernel.
// Index: ((mi * (K/16) + ki) * 32 + lane) -> uint4 (regs a0,a1,a2,a3)
__device__ uint4 g_xa[(M / 16) * (K / 16) * 32];

// ---------------- helpers ----------------

__device__ __forceinline__ uint32_t smem_u32(const void* p) {
    uint32_t a;
    asm("{ .reg .u64 t; cvta.to.shared.u64 t, %1; cvt.u32.u64 %0, t; }"
        : "=r"(a) : "l"(p));
    return a;
}

__device__ __forceinline__ uint32_t sw128(uint32_t off) {
    return off ^ ((off >> 3) & 0x70);
}

// Dequant one 16-weight group (4 int32, low byte each = 4 x 2-bit codes)
// into 8 u32 = 16 fp16, via a 4-entry fp16 LUT + PRMT byte gather.
__device__ __forceinline__ void dequant16(const int4& p4, float n, uint32_t o[8]) {
    uint32_t b1 = (uint32_t)__half_as_ushort(__float2half_rn(n));
    uint32_t b3 = (uint32_t)__half_as_ushort(__float2half_rn(n * (1.0f / 3.0f)));
    uint32_t loT = (b1 ^ 0x8000u) | ((b3 ^ 0x8000u) << 16);  // bytes: [-n][-n/3]
    uint32_t hiT = b3 | (b1 << 16);                          // bytes: [n/3][n]
    uint32_t pv[4] = { (uint32_t)p4.x, (uint32_t)p4.y, (uint32_t)p4.z, (uint32_t)p4.w };
    #pragma unroll
    for (int q = 0; q < 4; ++q) {
        uint32_t by = pv[q] & 0xFFu;   // 4 x 2-bit codes
        uint32_t l = by & 0xFu;
        uint32_t h = by >> 4;
        uint32_t c0 = (l & 3u) * 0x22u + (l & 0xCu) * 0x880u + 0x1010u;
        uint32_t c1 = (h & 3u) * 0x22u + (h & 0xCu) * 0x880u + 0x1010u;
        o[2 * q]     = __byte_perm(loT, hiT, c0);
        o[2 * q + 1] = __byte_perm(loT, hiT, c1);
    }
}

// ---------------- kernel 0: x fp32 -> A-fragment fp16 layout ----------------
// 2 independent fragments per thread (MLP 8) to cover DRAM latency.

__global__ void convert_x_frag(const float* __restrict__ x) {
    int g0 = blockIdx.x * blockDim.x + threadIdx.x;   // 0 .. 65535
    #pragma unroll
    for (int h = 0; h < 2; ++h) {
        int g = g0 + h * 65536;
        int lane = g & 31;
        int ki = (g >> 5) & (K / 16 - 1);
        int mi = g >> 13;
        int r = lane >> 2;
        int c = (lane & 3) * 2;
        const float* base = x + (size_t)(mi * 16 + r) * K + ki * 16 + c;
        float2 v00 = __ldg(reinterpret_cast<const float2*>(base));
        float2 v10 = __ldg(reinterpret_cast<const float2*>(base + 8 * K));
        float2 v01 = __ldg(reinterpret_cast<const float2*>(base + 8));
        float2 v11 = __ldg(reinterpret_cast<const float2*>(base + 8 * K + 8));
        uint4 o;
        o.x = (uint32_t)__half_as_ushort(__float2half_rn(v00.x)) |
              ((uint32_t)__half_as_ushort(__float2half_rn(v00.y)) << 16);
        o.y = (uint32_t)__half_as_ushort(__float2half_rn(v10.x)) |
              ((uint32_t)__half_as_ushort(__float2half_rn(v10.y)) << 16);
        o.z = (uint32_t)__half_as_ushort(__float2half_rn(v01.x)) |
              ((uint32_t)__half_as_ushort(__float2half_rn(v01.y)) << 16);
        o.w = (uint32_t)__half_as_ushort(__float2half_rn(v11.x)) |
              ((uint32_t)__half_as_ushort(__float2half_rn(v11.y)) << 16);
        g_xa[g] = o;
    }
}

// ---------------- kernel 1: fused dequant + fp16 HMMA GEMM ----------------
// Grid (128): blockIdx.x = N-tile (64 cols). CTA tile = 256(M) x 64(N), BK=128.
// Two independent 256-thread team pipelines (one per 64-wide k-chunk),
// synchronized by named barriers; teams share no SMEM in the main loop.
// si loop unrolled by 2 (B buffer base immediate); B swizzled read offsets
// precomputed once. End: drain cp.async, __syncthreads, team-1 -> team-0 add.

__global__ void __launch_bounds__(THREADS, 1)
linear2bit_gemm(const int4* __restrict__ wq,        // one int4 = one 16-value group
                const void* __restrict__ wn_raw,    // [NUM_GROUPS] norms (fp32 or fp16)
                const float* __restrict__ bias,     // [N]
                float* __restrict__ out)            // [M, N]
{
    extern __shared__ char smem[];
    const uint32_t sb = smem_u32(smem);
    const int tid = threadIdx.x;
    const int wid = tid >> 5;
    const int lid = tid & 31;
    const int ntile = blockIdx.x;                   // 64-col tile

    // ---- runtime dtype probe for weight_norm ----
    const float* wnf = (const float*)wn_raw;
    const __half* wnh = (const __half*)wn_raw;
    const float probe = __ldg(wnf);
    const bool norm_f32 = (probe > 6e-5f && probe < 0.06f);

    // team / compute-warp decomposition (teams interleaved across SMSPs)
    const int team = (wid >> 2) & 1;                       // k-chunk owner
    const int cwid = (wid & 3) | ((wid >> 3) << 2);        // 0..7 within team
    const int ttid = cwid * 32 + lid;                      // 0..255 within team
    const int warp_m = cwid >> 1;    // 4 x 64 rows
    const int warp_n = cwid & 1;     // 2 x 32 cols
    const int bar_id = 1 + team;     // named barrier per team

    // Precomputed swizzled B read offsets (relative to buffer base):
    // bsw[p][ks] = sw128(brow[p] + ks*32). Non-hoistable by algebra (XOR mask
    // overlaps the ks bits), so hold them in registers explicitly.
    uint32_t bsw[2][4];
    #pragma unroll
    for (int p = 0; p < 2; ++p) {
        uint32_t brow =
            (uint32_t)((warp_n * 32 + p * 16 + (lid & 15)) * 128 + (lid >> 4) * 16);
        #pragma unroll
        for (int ks = 0; ks < 4; ++ks)
            bsw[p][ks] = sw128(brow + (uint32_t)(ks * 32));
    }

    // ---- A cp.async (team-local: each team fills its own kc=team half) ----
    // src uint4 = si*256 + a_off0 + j*16384 ; dst = team half + ttid*16 + j*4096
    const uint32_t a_off0 =
        (uint32_t)((cwid >> 2) * 8192 + team * 128 + (cwid & 3) * 32 + lid);
    const uint32_t a_dst0 = (uint32_t)(team * 32768 + ttid * 16);
    auto cp_a = [&](int si, int slot) {
        const uint4* srcb = g_xa + (size_t)si * 256 + a_off0;
        uint32_t sdst = sb + SMEM_A + (uint32_t)slot * 65536u + a_dst0;
        #pragma unroll
        for (int j = 0; j < 8; ++j) {
            const uint4* src = srcb + j * 16384;
            asm volatile("cp.async.cg.shared.global [%0], [%1], 16;"
                         :: "r"(sdst + (uint32_t)j * 4096u), "l"(src) : "memory");
        }
        asm volatile("cp.async.commit_group;" ::: "memory");
    };

    // A LDS byte base within a stage for this warp/lane (team half + warp rows)
    const uint32_t a_lds_off =
        (uint32_t)team * 32768u + (uint32_t)((warp_m * 4 * 4) * 32 + lid) * 16u;

    float acc[4][4][4];
    #pragma unroll
    for (int mt = 0; mt < 4; ++mt)
        #pragma unroll
        for (int nt = 0; nt < 4; ++nt)
            #pragma unroll
            for (int e = 0; e < 4; ++e) acc[mt][nt][e] = 0.0f;

    // B staging (team-local): 256 groups per chunk over 256 team threads
    const int br = ttid >> 2;       // B row in tile (0..63)
    const int bj = ttid & 3;        // group within this team's k-chunk (0..3)
    const int bg_base = (ntile * 64 + br) * 256 + team * 4 + bj;   // + si*8
    const uint32_t b_sts0 = sw128((uint32_t)(br * 128 + bj * 32));
    const uint32_t b_sts1 = sw128((uint32_t)(br * 128 + bj * 32 + 16));

    int4  bv;
    float bn;

    auto ldg_b = [&](int si) {
        int gidx = bg_base + si * 8;
        bv = __ldg(wq + gidx);
        bn = norm_f32 ? __ldg(wnf + gidx) : __half2float(__ldg(wnh + gidx));
    };
    auto sts_b = [&](int b) {
        char* bbuf = smem + SMEM_B + b * 16384 + team * 8192;
        uint32_t o[8];
        dequant16(bv, bn, o);
        *reinterpret_cast<int4*>(bbuf + b_sts0) =
            make_int4((int)o[0], (int)o[1], (int)o[2], (int)o[3]);
        *reinterpret_cast<int4*>(bbuf + b_sts1) =
            make_int4((int)o[4], (int)o[5], (int)o[6], (int)o[7]);
    };

    // ---- prologue (team-local) ----
    ldg_b(0);
    cp_a(0, 0);
    cp_a(1, 1);
    sts_b(0);
    asm volatile("cp.async.wait_group 1;" ::: "memory");   // stage 0 (our half) ready
    asm volatile("bar.sync %0, %1;" :: "r"(bar_id), "n"(256) : "memory");

    int s_cur = 0;   // (si) % 3
    int s_nxt = 2;   // (si+2) % 3

    // one super-iteration body; b is a compile-time constant (0/1)
    auto body = [&](int si, int b) {
        if (si + 1 < SITERS) ldg_b(si + 1);

        const char* aslot = smem + SMEM_A + s_cur * 65536 + a_lds_off;
        const uint32_t bb = sb + SMEM_B + (uint32_t)(b * 16384) + (uint32_t)team * 8192u;

        #pragma unroll
        for (int ks = 0; ks < 4; ++ks) {
            // A fragments for this ks: 4 x LDS.128 (mt = 0..3)
            uint4 af[4];
            #pragma unroll
            for (int mt = 0; mt < 4; ++mt)
                af[mt] = *reinterpret_cast<const uint4*>(
                    aslot + (mt * 4 + ks) * 32 * 16);

            uint32_t bf[2][4];
            #pragma unroll
            for (int p = 0; p < 2; ++p) {
                uint32_t addr = bb + bsw[p][ks];
                asm volatile(
                    "ldmatrix.sync.aligned.m8n8.x4.shared.b16 {%0,%1,%2,%3}, [%4];"
                    : "=r"(bf[p][0]), "=r"(bf[p][1]), "=r"(bf[p][2]), "=r"(bf[p][3])
                    : "r"(addr));
            }
            #pragma unroll
            for (int mt = 0; mt < 4; ++mt) {
                #pragma unroll
                for (int nt = 0; nt < 4; ++nt) {
                    uint32_t b0 = bf[nt >> 1][nt & 1];
                    uint32_t b1 = bf[nt >> 1][(nt & 1) + 2];
                    asm volatile(
                        "mma.sync.aligned.m16n8k16.row.col.f32.f16.f16.f32 "
                        "{%0,%1,%2,%3}, {%4,%5,%6,%7}, {%8,%9}, {%0,%1,%2,%3};"
                        : "+f"(acc[mt][nt][0]), "+f"(acc[mt][nt][1]),
                          "+f"(acc[mt][nt][2]), "+f"(acc[mt][nt][3])
                        : "r"(af[mt].x), "r"(af[mt].y),
                          "r"(af[mt].z), "r"(af[mt].w),
                          "r"(b0), "r"(b1));
                }
            }
        }

        if (si + 1 < SITERS) sts_b(b ^ 1);

        // Issue our half of stage si+2; at the tail commit an EMPTY group so
        // wait_group 1 keeps counting correctly.
        if (si + 2 < SITERS) cp_a(si + 2, s_nxt);
        else asm volatile("cp.async.commit_group;" ::: "memory");
        asm volatile("cp.async.wait_group 1;" ::: "memory");   // stage si+1 ready
        asm volatile("bar.sync %0, %1;" :: "r"(bar_id), "n"(256) : "memory");

        s_cur = (s_cur == 2) ? 0 : s_cur + 1;
        s_nxt = (s_nxt == 2) ? 0 : s_nxt + 1;
    };

    #pragma unroll 1
    for (int si = 0; si < SITERS; si += 2) {
        body(si, 0);
        body(si + 1, 1);
    }

    // ---- drain the async pipe, then full-CTA sync before reusing the A ring ----
    asm volatile("cp.async.wait_group 0;" ::: "memory");
    __syncthreads();

    // ---- split-K reduction: team 1 -> smem -> team 0 adds ----
    // Reuse the A ring region. Per team-1 warp: 16 float4 chunks laid out
    // [chunk(16)][lane(32)] so loads are conflict-free.
    if (team == 1) {
        char* red = smem + SMEM_A + cwid * 8192 + lid * 16;
        #pragma unroll
        for (int mt = 0; mt < 4; ++mt)
            #pragma unroll
            for (int nt = 0; nt < 4; ++nt)
                *reinterpret_cast<float4*>(red + (mt * 4 + nt) * 512) =
                    make_float4(acc[mt][nt][0], acc[mt][nt][1],
                                acc[mt][nt][2], acc[mt][nt][3]);
    }
    __syncthreads();

    if (team == 0) {
        const char* red = smem + SMEM_A + cwid * 8192 + lid * 16;
        const int mbase = warp_m * 64;
        const int nbase = ntile * 64 + warp_n * 32;
        const int rq = lid >> 2;             // row within m16 (0..7)
        const int cq = (lid & 3) * 2;        // col within n8 (0,2,4,6)
        #pragma unroll
        for (int mt = 0; mt < 4; ++mt) {
            #pragma unroll
            for (int nt = 0; nt < 4; ++nt) {
                float4 r = *reinterpret_cast<const float4*>(red + (mt * 4 + nt) * 512);
                int m0 = mbase + mt * 16 + rq;
                int n0 = nbase + nt * 8 + cq;
                float2 bsv = __ldg(reinterpret_cast<const float2*>(bias + n0));
                float2 v0, v1;
                v0.x = acc[mt][nt][0] + r.x + bsv.x;
                v0.y = acc[mt][nt][1] + r.y + bsv.y;
                v1.x = acc[mt][nt][2] + r.z + bsv.x;
                v1.y = acc[mt][nt][3] + r.w + bsv.y;
                *reinterpret_cast<float2*>(out + (size_t)m0 * N + n0) = v0;
                *reinterpret_cast<float2*>(out + (size_t)(m0 + 8) * N + n0) = v1;
            }
        }
    }
}

// ---------------- launch ----------------

extern "C" void kernel_launch(void* const* d_in, const int* in_sizes, int n_in,
                              void* d_out, int out_size) {
    (void)in_sizes; (void)n_in; (void)out_size;
    const float* x    = (const float*)d_in[0];
    const int4*  wq   = (const int4*)d_in[1];    // [NUM_GROUPS] groups of 4 int32
    const void*  wn   = (const void*)d_in[2];    // [NUM_GROUPS] norms
    const float* bias = (const float*)d_in[3];
    float*       out  = (float*)d_out;

    cudaFuncSetAttribute(linear2bit_gemm,
                         cudaFuncAttributeMaxDynamicSharedMemorySize, SMEM_TOTAL);

    convert_x_frag<<<65536 / 256, 256>>>(x);
    linear2bit_gemm<<<N / 64, THREADS, SMEM_TOTAL>>>(wq, wn, bias, out);
}

// round 16
// speedup vs baseline: 1.0587x; 1.0408x over previous
#include <cuda_runtime.h>
#include <cuda_fp16.h>
#include <cstdint>

// Problem dims
static constexpr int M = 256;
static constexpr int K = 4096;
static constexpr int N = 8192;
static constexpr int SITERS = K / 128;    // 32 super-iters of BK=128
static constexpr int THREADS = 512;       // 16 warps: 4(M) x 2(N) x 2(K-team)

// SMEM layout (per 512-thread CTA, tile 256x64, BK=128):
//  [0,1024)              header (alignment)
//  [1024, +3*65536)      A fragment ring: 3 stages x 64KB
//                        stage = [kc(2)][mi(16)][ks(4)][lane(32)] x 16B
//  [197632, +2*16384)    B double buffer: per buffer 2 k-chunks x (64 rows x 128B)
static constexpr int SMEM_A = 1024;
static constexpr int SMEM_B = 1024 + 3 * 65536;        // 197632
static constexpr int SMEM_TOTAL = SMEM_B + 2 * 16384;  // 230400

// A in m16n8k16 fragment layout, fp16, built by convert kernel.
// Index: ((mi * (K/16) + ki) * 32 + lane) -> uint4 (regs a0,a1,a2,a3)
__device__ uint4 g_xa[(M / 16) * (K / 16) * 32];

// ---------------- helpers ----------------

__device__ __forceinline__ uint32_t smem_u32(const void* p) {
    uint32_t a;
    asm("{ .reg .u64 t; cvta.to.shared.u64 t, %1; cvt.u32.u64 %0, t; }"
        : "=r"(a) : "l"(p));
    return a;
}

__device__ __forceinline__ uint32_t sw128(uint32_t off) {
    return off ^ ((off >> 3) & 0x70);
}

// Dequant one 16-weight group (4 int32, low byte each = 4 x 2-bit codes)
// into 8 u32 = 16 fp16, via a 4-entry fp16 LUT + PRMT byte gather.
__device__ __forceinline__ void dequant16(const int4& p4, float n, uint32_t o[8]) {
    uint32_t b1 = (uint32_t)__half_as_ushort(__float2half_rn(n));
    uint32_t b3 = (uint32_t)__half_as_ushort(__float2half_rn(n * (1.0f / 3.0f)));
    uint32_t loT = (b1 ^ 0x8000u) | ((b3 ^ 0x8000u) << 16);  // bytes: [-n][-n/3]
    uint32_t hiT = b3 | (b1 << 16);                          // bytes: [n/3][n]
    uint32_t pv[4] = { (uint32_t)p4.x, (uint32_t)p4.y, (uint32_t)p4.z, (uint32_t)p4.w };
    #pragma unroll
    for (int q = 0; q < 4; ++q) {
        uint32_t by = pv[q] & 0xFFu;   // 4 x 2-bit codes
        uint32_t l = by & 0xFu;
        uint32_t h = by >> 4;
        uint32_t c0 = (l & 3u) * 0x22u + (l & 0xCu) * 0x880u + 0x1010u;
        uint32_t c1 = (h & 3u) * 0x22u + (h & 0xCu) * 0x880u + 0x1010u;
        o[2 * q]     = __byte_perm(loT, hiT, c0);
        o[2 * q + 1] = __byte_perm(loT, hiT, c1);
    }
}

// ---------------- kernel 0: x fp32 -> A-fragment fp16 layout ----------------
// 4 independent fragments per thread (MLP 16); 512-thread blocks, 64 blocks.

__global__ void __launch_bounds__(512, 2) convert_x_frag(const float* __restrict__ x) {
    int g0 = blockIdx.x * blockDim.x + threadIdx.x;   // 0 .. 32767
    #pragma unroll
    for (int h = 0; h < 4; ++h) {
        int g = g0 + h * 32768;
        int lane = g & 31;
        int ki = (g >> 5) & (K / 16 - 1);
        int mi = g >> 13;
        int r = lane >> 2;
        int c = (lane & 3) * 2;
        const float* base = x + (size_t)(mi * 16 + r) * K + ki * 16 + c;
        float2 v00 = __ldg(reinterpret_cast<const float2*>(base));
        float2 v10 = __ldg(reinterpret_cast<const float2*>(base + 8 * K));
        float2 v01 = __ldg(reinterpret_cast<const float2*>(base + 8));
        float2 v11 = __ldg(reinterpret_cast<const float2*>(base + 8 * K + 8));
        uint4 o;
        o.x = (uint32_t)__half_as_ushort(__float2half_rn(v00.x)) |
              ((uint32_t)__half_as_ushort(__float2half_rn(v00.y)) << 16);
        o.y = (uint32_t)__half_as_ushort(__float2half_rn(v10.x)) |
              ((uint32_t)__half_as_ushort(__float2half_rn(v10.y)) << 16);
        o.z = (uint32_t)__half_as_ushort(__float2half_rn(v01.x)) |
              ((uint32_t)__half_as_ushort(__float2half_rn(v01.y)) << 16);
        o.w = (uint32_t)__half_as_ushort(__float2half_rn(v11.x)) |
              ((uint32_t)__half_as_ushort(__float2half_rn(v11.y)) << 16);
        g_xa[g] = o;
    }
}

// ---------------- kernel 1: fused dequant + fp16 HMMA GEMM ----------------
// Grid (128): blockIdx.x = N-tile (64 cols). CTA tile = 256(M) x 64(N), BK=128.
// Two independent 256-thread team pipelines (one per 64-wide k-chunk),
// synchronized by named barriers; teams share no SMEM in the main loop.
// si loop unrolled by 2 (B buffer base immediate); B swizzled read offsets
// precomputed; B dequant+STS placed mid-ks-loop to overlap MMA drain.
// End: drain cp.async, __syncthreads, team-1 -> team-0 add.

__global__ void __launch_bounds__(THREADS, 1)
linear2bit_gemm(const int4* __restrict__ wq,        // one int4 = one 16-value group
                const void* __restrict__ wn_raw,    // [NUM_GROUPS] norms (fp32 or fp16)
                const float* __restrict__ bias,     // [N]
                float* __restrict__ out)            // [M, N]
{
    extern __shared__ char smem[];
    const uint32_t sb = smem_u32(smem);
    const int tid = threadIdx.x;
    const int wid = tid >> 5;
    const int lid = tid & 31;
    const int ntile = blockIdx.x;                   // 64-col tile

    // ---- runtime dtype probe for weight_norm ----
    const float* wnf = (const float*)wn_raw;
    const __half* wnh = (const __half*)wn_raw;
    const float probe = __ldg(wnf);
    const bool norm_f32 = (probe > 6e-5f && probe < 0.06f);

    // team / compute-warp decomposition (teams interleaved across SMSPs)
    const int team = (wid >> 2) & 1;                       // k-chunk owner
    const int cwid = (wid & 3) | ((wid >> 3) << 2);        // 0..7 within team
    const int ttid = cwid * 32 + lid;                      // 0..255 within team
    const int warp_m = cwid >> 1;    // 4 x 64 rows
    const int warp_n = cwid & 1;     // 2 x 32 cols
    const int bar_id = 1 + team;     // named barrier per team

    // Precomputed swizzled B read offsets (relative to buffer base)
    uint32_t bsw[2][4];
    #pragma unroll
    for (int p = 0; p < 2; ++p) {
        uint32_t brow =
            (uint32_t)((warp_n * 32 + p * 16 + (lid & 15)) * 128 + (lid >> 4) * 16);
        #pragma unroll
        for (int ks = 0; ks < 4; ++ks)
            bsw[p][ks] = sw128(brow + (uint32_t)(ks * 32));
    }

    // ---- A cp.async (team-local: each team fills its own kc=team half) ----
    const uint32_t a_off0 =
        (uint32_t)((cwid >> 2) * 8192 + team * 128 + (cwid & 3) * 32 + lid);
    const uint32_t a_dst0 = (uint32_t)(team * 32768 + ttid * 16);
    auto cp_a = [&](int si, int slot) {
        const uint4* srcb = g_xa + (size_t)si * 256 + a_off0;
        uint32_t sdst = sb + SMEM_A + (uint32_t)slot * 65536u + a_dst0;
        #pragma unroll
        for (int j = 0; j < 8; ++j) {
            const uint4* src = srcb + j * 16384;
            asm volatile("cp.async.cg.shared.global [%0], [%1], 16;"
                         :: "r"(sdst + (uint32_t)j * 4096u), "l"(src) : "memory");
        }
        asm volatile("cp.async.commit_group;" ::: "memory");
    };

    // A LDS byte base within a stage for this warp/lane (team half + warp rows)
    const uint32_t a_lds_off =
        (uint32_t)team * 32768u + (uint32_t)((warp_m * 4 * 4) * 32 + lid) * 16u;

    float acc[4][4][4];
    #pragma unroll
    for (int mt = 0; mt < 4; ++mt)
        #pragma unroll
        for (int nt = 0; nt < 4; ++nt)
            #pragma unroll
            for (int e = 0; e < 4; ++e) acc[mt][nt][e] = 0.0f;

    // B staging (team-local): 256 groups per chunk over 256 team threads
    const int br = ttid >> 2;       // B row in tile (0..63)
    const int bj = ttid & 3;        // group within this team's k-chunk (0..3)
    const int bg_base = (ntile * 64 + br) * 256 + team * 4 + bj;   // + si*8
    const uint32_t b_sts0 = sw128((uint32_t)(br * 128 + bj * 32));
    const uint32_t b_sts1 = sw128((uint32_t)(br * 128 + bj * 32 + 16));

    int4  bv;
    float bn;

    auto ldg_b = [&](int si) {
        int gidx = bg_base + si * 8;
        bv = __ldcg(wq + gidx);                           // streamed once: bypass L1
        bn = norm_f32 ? __ldcg(wnf + gidx)
                      : __half2float(__ldcg(wnh + gidx));
    };
    auto sts_b = [&](int b) {
        char* bbuf = smem + SMEM_B + b * 16384 + team * 8192;
        uint32_t o[8];
        dequant16(bv, bn, o);
        *reinterpret_cast<int4*>(bbuf + b_sts0) =
            make_int4((int)o[0], (int)o[1], (int)o[2], (int)o[3]);
        *reinterpret_cast<int4*>(bbuf + b_sts1) =
            make_int4((int)o[4], (int)o[5], (int)o[6], (int)o[7]);
    };

    // ---- prologue (team-local) ----
    ldg_b(0);
    cp_a(0, 0);
    cp_a(1, 1);
    sts_b(0);
    asm volatile("cp.async.wait_group 1;" ::: "memory");   // stage 0 (our half) ready
    asm volatile("bar.sync %0, %1;" :: "r"(bar_id), "n"(256) : "memory");

    int s_cur = 0;   // (si) % 3
    int s_nxt = 2;   // (si+2) % 3

    // one ks step of the compute
    auto ks_step = [&](const char* aslot, uint32_t bb, int ks) {
        uint4 af[4];
        #pragma unroll
        for (int mt = 0; mt < 4; ++mt)
            af[mt] = *reinterpret_cast<const uint4*>(
                aslot + (mt * 4 + ks) * 32 * 16);

        uint32_t bf[2][4];
        #pragma unroll
        for (int p = 0; p < 2; ++p) {
            uint32_t addr = bb + bsw[p][ks];
            asm volatile(
                "ldmatrix.sync.aligned.m8n8.x4.shared.b16 {%0,%1,%2,%3}, [%4];"
                : "=r"(bf[p][0]), "=r"(bf[p][1]), "=r"(bf[p][2]), "=r"(bf[p][3])
                : "r"(addr));
        }
        #pragma unroll
        for (int mt = 0; mt < 4; ++mt) {
            #pragma unroll
            for (int nt = 0; nt < 4; ++nt) {
                uint32_t b0 = bf[nt >> 1][nt & 1];
                uint32_t b1 = bf[nt >> 1][(nt & 1) + 2];
                asm volatile(
                    "mma.sync.aligned.m16n8k16.row.col.f32.f16.f16.f32 "
                    "{%0,%1,%2,%3}, {%4,%5,%6,%7}, {%8,%9}, {%0,%1,%2,%3};"
                    : "+f"(acc[mt][nt][0]), "+f"(acc[mt][nt][1]),
                      "+f"(acc[mt][nt][2]), "+f"(acc[mt][nt][3])
                    : "r"(af[mt].x), "r"(af[mt].y),
                      "r"(af[mt].z), "r"(af[mt].w),
                      "r"(b0), "r"(b1));
            }
        }
    };

    // one super-iteration body; b is a compile-time constant (0/1)
    auto body = [&](int si, int b) {
        if (si + 1 < SITERS) ldg_b(si + 1);

        const char* aslot = smem + SMEM_A + s_cur * 65536 + a_lds_off;
        const uint32_t bb = sb + SMEM_B + (uint32_t)(b * 16384) + (uint32_t)team * 8192u;

        ks_step(aslot, bb, 0);
        ks_step(aslot, bb, 1);
        // Dequant + STS for next iter mid-loop: ALU overlaps MMA drain.
        if (si + 1 < SITERS) sts_b(b ^ 1);
        ks_step(aslot, bb, 2);
        ks_step(aslot, bb, 3);

        // Issue our half of stage si+2; at the tail commit an EMPTY group so
        // wait_group 1 keeps counting correctly.
        if (si + 2 < SITERS) cp_a(si + 2, s_nxt);
        else asm volatile("cp.async.commit_group;" ::: "memory");
        asm volatile("cp.async.wait_group 1;" ::: "memory");   // stage si+1 ready
        asm volatile("bar.sync %0, %1;" :: "r"(bar_id), "n"(256) : "memory");

        s_cur = (s_cur == 2) ? 0 : s_cur + 1;
        s_nxt = (s_nxt == 2) ? 0 : s_nxt + 1;
    };

    #pragma unroll 1
    for (int si = 0; si < SITERS; si += 2) {
        body(si, 0);
        body(si + 1, 1);
    }

    // ---- drain the async pipe, then full-CTA sync before reusing the A ring ----
    asm volatile("cp.async.wait_group 0;" ::: "memory");
    __syncthreads();

    // ---- split-K reduction: team 1 -> smem -> team 0 adds ----
    if (team == 1) {
        char* red = smem + SMEM_A + cwid * 8192 + lid * 16;
        #pragma unroll
        for (int mt = 0; mt < 4; ++mt)
            #pragma unroll
            for (int nt = 0; nt < 4; ++nt)
                *reinterpret_cast<float4*>(red + (mt * 4 + nt) * 512) =
                    make_float4(acc[mt][nt][0], acc[mt][nt][1],
                                acc[mt][nt][2], acc[mt][nt][3]);
    }
    __syncthreads();

    if (team == 0) {
        const char* red = smem + SMEM_A + cwid * 8192 + lid * 16;
        const int mbase = warp_m * 64;
        const int nbase = ntile * 64 + warp_n * 32;
        const int rq = lid >> 2;             // row within m16 (0..7)
        const int cq = (lid & 3) * 2;        // col within n8 (0,2,4,6)
        #pragma unroll
        for (int mt = 0; mt < 4; ++mt) {
            #pragma unroll
            for (int nt = 0; nt < 4; ++nt) {
                float4 r = *reinterpret_cast<const float4*>(red + (mt * 4 + nt) * 512);
                int m0 = mbase + mt * 16 + rq;
                int n0 = nbase + nt * 8 + cq;
                float2 bsv = __ldg(reinterpret_cast<const float2*>(bias + n0));
                float2 v0, v1;
                v0.x = acc[mt][nt][0] + r.x + bsv.x;
                v0.y = acc[mt][nt][1] + r.y + bsv.y;
                v1.x = acc[mt][nt][2] + r.z + bsv.x;
                v1.y = acc[mt][nt][3] + r.w + bsv.y;
                *reinterpret_cast<float2*>(out + (size_t)m0 * N + n0) = v0;
                *reinterpret_cast<float2*>(out + (size_t)(m0 + 8) * N + n0) = v1;
            }
        }
    }
}

// ---------------- launch ----------------

extern "C" void kernel_launch(void* const* d_in, const int* in_sizes, int n_in,
                              void* d_out, int out_size) {
    (void)in_sizes; (void)n_in; (void)out_size;
    const float* x    = (const float*)d_in[0];
    const int4*  wq   = (const int4*)d_in[1];    // [NUM_GROUPS] groups of 4 int32
    const void*  wn   = (const void*)d_in[2];    // [NUM_GROUPS] norms
    const float* bias = (const float*)d_in[3];
    float*       out  = (float*)d_out;

    cudaFuncSetAttribute(linear2bit_gemm,
                         cudaFuncAttributeMaxDynamicSharedMemorySize, SMEM_TOTAL);

    convert_x_frag<<<64, 512>>>(x);
    linear2bit_gemm<<<N / 64, THREADS, SMEM_TOTAL>>>(wq, wn, bias, out);
}

// round 17
// speedup vs baseline: 1.0645x; 1.0055x over previous
#include <cuda_runtime.h>
#include <cuda_fp16.h>
#include <cstdint>

// Problem dims
static constexpr int M = 256;
static constexpr int K = 4096;
static constexpr int N = 8192;
static constexpr int SITERS = K / 128;    // 32 super-iters of BK=128
static constexpr int THREADS = 256;       // 8 warps: 2 K-teams x 4 M-warps, warp tile 64x64

// SMEM layout (per 256-thread CTA, tile 256x64, BK=128):
//  [0,1024)              header (alignment)
//  [1024, +3*65536)      A fragment ring: 3 stages x 64KB
//                        stage = [kc(2)][mi(16)][ks(4)][lane(32)] x 16B
//  [197632, +2*16384)    B double buffer: per buffer 2 k-chunks x (64 rows x 128B)
static constexpr int SMEM_A = 1024;
static constexpr int SMEM_B = 1024 + 3 * 65536;        // 197632
static constexpr int SMEM_TOTAL = SMEM_B + 2 * 16384;  // 230400

// A in m16n8k16 fragment layout, fp16, built by convert kernel.
// Index: ((mi * (K/16) + ki) * 32 + lane) -> uint4 (regs a0,a1,a2,a3)
__device__ uint4 g_xa[(M / 16) * (K / 16) * 32];

// ---------------- helpers ----------------

__device__ __forceinline__ uint32_t smem_u32(const void* p) {
    uint32_t a;
    asm("{ .reg .u64 t; cvta.to.shared.u64 t, %1; cvt.u32.u64 %0, t; }"
        : "=r"(a) : "l"(p));
    return a;
}

__device__ __forceinline__ uint32_t sw128(uint32_t off) {
    return off ^ ((off >> 3) & 0x70);
}

// Dequant one 16-weight group (4 int32, low byte each = 4 x 2-bit codes)
// into 8 u32 = 16 fp16, via a 4-entry fp16 LUT + PRMT byte gather.
__device__ __forceinline__ void dequant16(const int4& p4, float n, uint32_t o[8]) {
    uint32_t b1 = (uint32_t)__half_as_ushort(__float2half_rn(n));
    uint32_t b3 = (uint32_t)__half_as_ushort(__float2half_rn(n * (1.0f / 3.0f)));
    uint32_t loT = (b1 ^ 0x8000u) | ((b3 ^ 0x8000u) << 16);  // bytes: [-n][-n/3]
    uint32_t hiT = b3 | (b1 << 16);                          // bytes: [n/3][n]
    uint32_t pv[4] = { (uint32_t)p4.x, (uint32_t)p4.y, (uint32_t)p4.z, (uint32_t)p4.w };
    #pragma unroll
    for (int q = 0; q < 4; ++q) {
        uint32_t by = pv[q] & 0xFFu;   // 4 x 2-bit codes
        uint32_t l = by & 0xFu;
        uint32_t h = by >> 4;
        uint32_t c0 = (l & 3u) * 0x22u + (l & 0xCu) * 0x880u + 0x1010u;
        uint32_t c1 = (h & 3u) * 0x22u + (h & 0xCu) * 0x880u + 0x1010u;
        o[2 * q]     = __byte_perm(loT, hiT, c0);
        o[2 * q + 1] = __byte_perm(loT, hiT, c1);
    }
}

// ---------------- kernel 0: x fp32 -> A-fragment fp16 layout ----------------
// 4 independent fragments per thread (MLP 16); 512-thread blocks, 64 blocks.

__global__ void __launch_bounds__(512, 2) convert_x_frag(const float* __restrict__ x) {
    int g0 = blockIdx.x * blockDim.x + threadIdx.x;   // 0 .. 32767
    #pragma unroll
    for (int h = 0; h < 4; ++h) {
        int g = g0 + h * 32768;
        int lane = g & 31;
        int ki = (g >> 5) & (K / 16 - 1);
        int mi = g >> 13;
        int r = lane >> 2;
        int c = (lane & 3) * 2;
        const float* base = x + (size_t)(mi * 16 + r) * K + ki * 16 + c;
        float2 v00 = __ldg(reinterpret_cast<const float2*>(base));
        float2 v10 = __ldg(reinterpret_cast<const float2*>(base + 8 * K));
        float2 v01 = __ldg(reinterpret_cast<const float2*>(base + 8));
        float2 v11 = __ldg(reinterpret_cast<const float2*>(base + 8 * K + 8));
        uint4 o;
        o.x = (uint32_t)__half_as_ushort(__float2half_rn(v00.x)) |
              ((uint32_t)__half_as_ushort(__float2half_rn(v00.y)) << 16);
        o.y = (uint32_t)__half_as_ushort(__float2half_rn(v10.x)) |
              ((uint32_t)__half_as_ushort(__float2half_rn(v10.y)) << 16);
        o.z = (uint32_t)__half_as_ushort(__float2half_rn(v01.x)) |
              ((uint32_t)__half_as_ushort(__float2half_rn(v01.y)) << 16);
        o.w = (uint32_t)__half_as_ushort(__float2half_rn(v11.x)) |
              ((uint32_t)__half_as_ushort(__float2half_rn(v11.y)) << 16);
        g_xa[g] = o;
    }
}

// ---------------- kernel 1: fused dequant + fp16 HMMA GEMM ----------------
// Grid (128): blockIdx.x = N-tile (64 cols). CTA tile = 256(M) x 64(N), BK=128.
// 8 warps: team = wid>>2 owns k-chunk [team*64, +64); within a team 4 warps,
// warp tile 64(M) x 64(N) — every A fragment read by exactly ONE warp, B by 4.
// Two independent team pipelines synced by named barriers (128 threads each).
// A: cp.async ring (3 stages x 64KB, team fills its own half, 2 iters ahead).
// B: packed LDG (L1-bypass) 1 iter ahead -> dequant -> SMEM (SW128), 2 buffers.
// End: drain cp.async, __syncthreads, team-1 accs -> smem -> team 0 adds.

__global__ void __launch_bounds__(THREADS, 1)
linear2bit_gemm(const int4* __restrict__ wq,        // one int4 = one 16-value group
                const void* __restrict__ wn_raw,    // [NUM_GROUPS] norms (fp32 or fp16)
                const float* __restrict__ bias,     // [N]
                float* __restrict__ out)            // [M, N]
{
    extern __shared__ char smem[];
    const uint32_t sb = smem_u32(smem);
    const int tid = threadIdx.x;
    const int wid = tid >> 5;
    const int lid = tid & 31;
    const int ntile = blockIdx.x;                   // 64-col tile

    // ---- runtime dtype probe for weight_norm ----
    const float* wnf = (const float*)wn_raw;
    const __half* wnh = (const __half*)wn_raw;
    const float probe = __ldg(wnf);
    const bool norm_f32 = (probe > 6e-5f && probe < 0.06f);

    // team / warp decomposition: one warp of each team per SMSP (wid%4 pairs)
    const int team = wid >> 2;                     // k-chunk owner (0/1)
    const int cwid = wid & 3;                      // M-warp within team (0..3)
    const int ttid = cwid * 32 + lid;              // 0..127 within team
    const int bar_id = 1 + team;                   // named barrier per team

    // B ldmatrix per-lane unswizzled bases (four 16-row groups; warp owns all 64 rows)
    uint32_t brow[4];
    #pragma unroll
    for (int p = 0; p < 4; ++p)
        brow[p] = (uint32_t)((p * 16 + (lid & 15)) * 128 + (lid >> 4) * 16);

    // ---- A cp.async (team fills its own kc=team half: 32KB, 16 chunks/thread) ----
    // flat = ttid + 128j -> ks = cwid, mi = j, lane = lid.
    // src uint4 = si*256 + [j*8192 + team*128 + cwid*32 + lid]
    // dst byte  = team*32768 + cwid*512 + lid*16 + j*2048
    const uint32_t a_off0 =
        (uint32_t)(team * 128 + cwid * 32 + lid);
    const uint32_t a_dst0 =
        (uint32_t)(team * 32768 + cwid * 512 + lid * 16);
    auto cp_a = [&](int si, int slot) {
        const uint4* srcb = g_xa + (size_t)si * 256 + a_off0;
        uint32_t sdst = sb + SMEM_A + (uint32_t)slot * 65536u + a_dst0;
        #pragma unroll
        for (int j = 0; j < 16; ++j) {
            const uint4* src = srcb + j * 8192;
            asm volatile("cp.async.cg.shared.global [%0], [%1], 16;"
                         :: "r"(sdst + (uint32_t)j * 2048u), "l"(src) : "memory");
        }
        asm volatile("cp.async.commit_group;" ::: "memory");
    };

    // A LDS byte base within a stage: warp reads mi = cwid*4 + mt, all 4 ks.
    // chunk byte = team*32768 + cwid*8192 + mt*2048 + ks*512 + lid*16
    const uint32_t a_lds_off =
        (uint32_t)(team * 32768 + cwid * 8192 + lid * 16);

    float acc[4][8][4];
    #pragma unroll
    for (int mt = 0; mt < 4; ++mt)
        #pragma unroll
        for (int nt = 0; nt < 8; ++nt)
            #pragma unroll
            for (int e = 0; e < 4; ++e) acc[mt][nt][e] = 0.0f;

    // B staging (team-local): 256 groups per chunk over 128 team threads (2 each)
    int bg_base[2];
    uint32_t b_sts0[2], b_sts1[2];
    #pragma unroll
    for (int i = 0; i < 2; ++i) {
        int gi = ttid + 128 * i;
        int br = gi >> 2;           // B row (0..63)
        int bj = gi & 3;            // group within k-chunk (0..3)
        bg_base[i] = (ntile * 64 + br) * 256 + team * 4 + bj;   // + si*8
        b_sts0[i] = sw128((uint32_t)(br * 128 + bj * 32));
        b_sts1[i] = sw128((uint32_t)(br * 128 + bj * 32 + 16));
    }

    int4  bv[2];
    float bn[2];

    auto ldg_b = [&](int si) {
        #pragma unroll
        for (int i = 0; i < 2; ++i) {
            int gidx = bg_base[i] + si * 8;
            bv[i] = __ldcg(wq + gidx);
            bn[i] = norm_f32 ? __ldcg(wnf + gidx)
                             : __half2float(__ldcg(wnh + gidx));
        }
    };
    auto sts_b = [&](int b) {
        char* bbuf = smem + SMEM_B + b * 16384 + team * 8192;
        #pragma unroll
        for (int i = 0; i < 2; ++i) {
            uint32_t o[8];
            dequant16(bv[i], bn[i], o);
            *reinterpret_cast<int4*>(bbuf + b_sts0[i]) =
                make_int4((int)o[0], (int)o[1], (int)o[2], (int)o[3]);
            *reinterpret_cast<int4*>(bbuf + b_sts1[i]) =
                make_int4((int)o[4], (int)o[5], (int)o[6], (int)o[7]);
        }
    };

    // ---- prologue (team-local) ----
    ldg_b(0);
    cp_a(0, 0);
    cp_a(1, 1);
    sts_b(0);
    asm volatile("cp.async.wait_group 1;" ::: "memory");   // stage 0 (our half) ready
    asm volatile("bar.sync %0, %1;" :: "r"(bar_id), "n"(128) : "memory");

    int s_cur = 0;   // (si) % 3
    int s_nxt = 2;   // (si+2) % 3

    // one ks step: 4 A LDS + 4 B ldmatrix + 32 MMAs
    auto ks_step = [&](const char* aslot, uint32_t bb, int ks) {
        uint4 af[4];
        #pragma unroll
        for (int mt = 0; mt < 4; ++mt)
            af[mt] = *reinterpret_cast<const uint4*>(
                aslot + mt * 2048 + ks * 512);

        uint32_t bf[4][4];
        #pragma unroll
        for (int p = 0; p < 4; ++p) {
            uint32_t addr = bb + sw128(brow[p] + (uint32_t)(ks * 32));
            asm volatile(
                "ldmatrix.sync.aligned.m8n8.x4.shared.b16 {%0,%1,%2,%3}, [%4];"
                : "=r"(bf[p][0]), "=r"(bf[p][1]), "=r"(bf[p][2]), "=r"(bf[p][3])
                : "r"(addr));
        }
        #pragma unroll
        for (int mt = 0; mt < 4; ++mt) {
            #pragma unroll
            for (int nt = 0; nt < 8; ++nt) {
                uint32_t b0 = bf[nt >> 1][nt & 1];
                uint32_t b1 = bf[nt >> 1][(nt & 1) + 2];
                asm volatile(
                    "mma.sync.aligned.m16n8k16.row.col.f32.f16.f16.f32 "
                    "{%0,%1,%2,%3}, {%4,%5,%6,%7}, {%8,%9}, {%0,%1,%2,%3};"
                    : "+f"(acc[mt][nt][0]), "+f"(acc[mt][nt][1]),
                      "+f"(acc[mt][nt][2]), "+f"(acc[mt][nt][3])
                    : "r"(af[mt].x), "r"(af[mt].y),
                      "r"(af[mt].z), "r"(af[mt].w),
                      "r"(b0), "r"(b1));
            }
        }
    };

    // one super-iteration body; b is a compile-time constant (0/1)
    auto body = [&](int si, int b) {
        if (si + 1 < SITERS) ldg_b(si + 1);

        const char* aslot = smem + SMEM_A + s_cur * 65536 + a_lds_off;
        const uint32_t bb = sb + SMEM_B + (uint32_t)(b * 16384) + (uint32_t)team * 8192u;

        ks_step(aslot, bb, 0);
        ks_step(aslot, bb, 1);
        // Dequant + STS for next iter mid-loop: ALU overlaps MMA drain.
        if (si + 1 < SITERS) sts_b(b ^ 1);
        ks_step(aslot, bb, 2);
        ks_step(aslot, bb, 3);

        // Issue our half of stage si+2; at the tail commit an EMPTY group so
        // wait_group 1 keeps counting correctly.
        if (si + 2 < SITERS) cp_a(si + 2, s_nxt);
        else asm volatile("cp.async.commit_group;" ::: "memory");
        asm volatile("cp.async.wait_group 1;" ::: "memory");   // stage si+1 ready
        asm volatile("bar.sync %0, %1;" :: "r"(bar_id), "n"(128) : "memory");

        s_cur = (s_cur == 2) ? 0 : s_cur + 1;
        s_nxt = (s_nxt == 2) ? 0 : s_nxt + 1;
    };

    #pragma unroll 1
    for (int si = 0; si < SITERS; si += 2) {
        body(si, 0);
        body(si + 1, 1);
    }

    // ---- drain the async pipe, then full-CTA sync before reusing the A ring ----
    asm volatile("cp.async.wait_group 0;" ::: "memory");
    __syncthreads();

    // ---- split-K reduction: team 1 -> smem -> team 0 adds ----
    // Reuse the A ring region. Per team-1 warp: 32 float4 chunks laid out
    // [chunk(32)][lane(32)] so loads are conflict-free (4 warps x 16KB = 64KB).
    if (team == 1) {
        char* red = smem + SMEM_A + cwid * 16384 + lid * 16;
        #pragma unroll
        for (int mt = 0; mt < 4; ++mt)
            #pragma unroll
            for (int nt = 0; nt < 8; ++nt)
                *reinterpret_cast<float4*>(red + (mt * 8 + nt) * 512) =
                    make_float4(acc[mt][nt][0], acc[mt][nt][1],
                                acc[mt][nt][2], acc[mt][nt][3]);
    }
    __syncthreads();

    if (team == 0) {
        const char* red = smem + SMEM_A + cwid * 16384 + lid * 16;
        const int mbase = cwid * 64;
        const int nbase = ntile * 64;
        const int rq = lid >> 2;             // row within m16 (0..7)
        const int cq = (lid & 3) * 2;        // col within n8 (0,2,4,6)
        #pragma unroll
        for (int mt = 0; mt < 4; ++mt) {
            #pragma unroll
            for (int nt = 0; nt < 8; ++nt) {
                float4 r = *reinterpret_cast<const float4*>(red + (mt * 8 + nt) * 512);
                int m0 = mbase + mt * 16 + rq;
                int n0 = nbase + nt * 8 + cq;
                float2 bsv = __ldg(reinterpret_cast<const float2*>(bias + n0));
                float2 v0, v1;
                v0.x = acc[mt][nt][0] + r.x + bsv.x;
                v0.y = acc[mt][nt][1] + r.y + bsv.y;
                v1.x = acc[mt][nt][2] + r.z + bsv.x;
                v1.y = acc[mt][nt][3] + r.w + bsv.y;
                *reinterpret_cast<float2*>(out + (size_t)m0 * N + n0) = v0;
                *reinterpret_cast<float2*>(out + (size_t)(m0 + 8) * N + n0) = v1;
            }
        }
    }
}

// ---------------- launch ----------------

extern "C" void kernel_launch(void* const* d_in, const int* in_sizes, int n_in,
                              void* d_out, int out_size) {
    (void)in_sizes; (void)n_in; (void)out_size;
    const float* x    = (const float*)d_in[0];
    const int4*  wq   = (const int4*)d_in[1];    // [NUM_GROUPS] groups of 4 int32
    const void*  wn   = (const void*)d_in[2];    // [NUM_GROUPS] norms
    const float* bias = (const float*)d_in[3];
    float*       out  = (float*)d_out;

    cudaFuncSetAttribute(linear2bit_gemm,
                         cudaFuncAttributeMaxDynamicSharedMemorySize, SMEM_TOTAL);

    convert_x_frag<<<64, 512>>>(x);
    linear2bit_gemm<<<N / 64, THREADS, SMEM_TOTAL>>>(wq, wn, bias, out);
}